// round 2
// baseline (speedup 1.0000x reference)
#include <cuda_runtime.h>
#include <math.h>

// BiRNN (2-layer bidirectional LSTM), B=32, T=512, H=1024.
// Round 2: same fp32 math as round 1, but the 512 per-step launches per layer
// are replaced by ONE persistent kernel per layer with a software grid barrier
// (128 blocks <= 148 SMs, all co-resident). Graph: 4 kernel nodes total.

#define Bsz 32
#define Tsz 512
#define Hsz 1024
#define G4  4096
#define MROWS (Tsz * Bsz) // 16384

// Scratch (device globals; no runtime allocation allowed).
__device__ float g_G[2][(size_t)MROWS * G4];    // [dir][t*B + b][4H] input-part gates + bias
__device__ float g_seq[2][(size_t)MROWS * Hsz]; // [dir][t*B + b][H]  layer-0 hidden outputs
__device__ float g_h[2][2][Bsz * Hsz];          // [parity][dir][b*H + h]
__device__ float g_c[2][Bsz * Hsz];             // [dir][b*H + h]

// Software grid barrier state. cnt returns to 0 after each barrier; gen is
// monotonically increasing across steps/replays (only compared for change).
__device__ unsigned int g_bar_cnt = 0;
__device__ volatile unsigned int g_bar_gen = 0;

__device__ __forceinline__ void grid_barrier(unsigned nb) {
    __syncthreads();
    if (threadIdx.x == 0) {
        __threadfence();                       // publish this block's stores
        unsigned gen = g_bar_gen;
        if (atomicAdd(&g_bar_cnt, 1u) == nb - 1) {
            g_bar_cnt = 0;                     // reset BEFORE release
            __threadfence();
            g_bar_gen = gen + 1;               // release
        } else {
            while (g_bar_gen == gen) { }
        }
        __threadfence();
    }
    __syncthreads();
}

// ---------------------------------------------------------------------------
// Big input GEMM: G[d][r][j] = sum_k A[r][k] * Wih_d[layer][j][k] + bias[j]
// r = t*B + b.  layer 0: A row = x[b][t][:]; layer 1: A row = g_seq[d][r][:].
// Block tile 64x64, K-tile 16, 256 threads, 4x4 per thread.
// ---------------------------------------------------------------------------
__global__ void __launch_bounds__(256) big_gemm_kernel(
    const float* __restrict__ x,
    const float* __restrict__ Wih_f, const float* __restrict__ b_f,
    const float* __restrict__ Wih_b, const float* __restrict__ b_b,
    int layer)
{
    const int d = blockIdx.z;
    const float* __restrict__ W    = (d == 0 ? Wih_f : Wih_b) + (size_t)layer * G4 * Hsz;
    const float* __restrict__ bias = (d == 0 ? b_f  : b_b ) + (size_t)layer * G4;

    const int rowBlk = blockIdx.y * 64;
    const int colBlk = blockIdx.x * 64;
    const int tid = threadIdx.x;

    __shared__ float As[16][68];
    __shared__ float Bs[16][68];

    const int lr = tid >> 2;        // 0..63 : local row (A) / local col (B)
    const int kv = (tid & 3) << 2;  // 0,4,8,12

    const int gr = rowBlk + lr;
    const float* __restrict__ aRow;
    if (layer == 0) aRow = x + ((size_t)(gr & 31) * Tsz + (gr >> 5)) * Hsz;
    else            aRow = g_seq[d] + (size_t)gr * Hsz;
    const float* __restrict__ bRow = W + (size_t)(colBlk + lr) * Hsz;

    const int ty = tid >> 4;   // 0..15 (row group)
    const int tx = tid & 15;   // 0..15 (col group)

    float acc[4][4] = {};

    for (int k0 = 0; k0 < Hsz; k0 += 16) {
        float4 av = *(const float4*)(aRow + k0 + kv);
        float4 bv = *(const float4*)(bRow + k0 + kv);
        As[kv + 0][lr] = av.x; As[kv + 1][lr] = av.y;
        As[kv + 2][lr] = av.z; As[kv + 3][lr] = av.w;
        Bs[kv + 0][lr] = bv.x; Bs[kv + 1][lr] = bv.y;
        Bs[kv + 2][lr] = bv.z; Bs[kv + 3][lr] = bv.w;
        __syncthreads();
#pragma unroll
        for (int kk = 0; kk < 16; kk++) {
            float4 a = *(const float4*)&As[kk][ty * 4];
            float4 b = *(const float4*)&Bs[kk][tx * 4];
            acc[0][0] += a.x * b.x; acc[0][1] += a.x * b.y;
            acc[0][2] += a.x * b.z; acc[0][3] += a.x * b.w;
            acc[1][0] += a.y * b.x; acc[1][1] += a.y * b.y;
            acc[1][2] += a.y * b.z; acc[1][3] += a.y * b.w;
            acc[2][0] += a.z * b.x; acc[2][1] += a.z * b.y;
            acc[2][2] += a.z * b.z; acc[2][3] += a.z * b.w;
            acc[3][0] += a.w * b.x; acc[3][1] += a.w * b.y;
            acc[3][2] += a.w * b.z; acc[3][3] += a.w * b.w;
        }
        __syncthreads();
    }

    float* __restrict__ out = g_G[d];
#pragma unroll
    for (int i = 0; i < 4; i++) {
        int r = rowBlk + ty * 4 + i;
#pragma unroll
        for (int j = 0; j < 4; j++) {
            int c = colBlk + tx * 4 + j;
            out[(size_t)r * G4 + c] = acc[i][j] + bias[c];
        }
    }
}

// ---------------------------------------------------------------------------
// Persistent recurrent kernel: grid (64, 2) = 128 blocks, 128 threads.
// blockIdx.y = direction. Loops over all 512 time steps with a grid barrier
// between steps. Per step, per direction:
//   gates[b][j] = g_G[d][t][b][j] + sum_k h_prev[b][k] * Whh[j][k]
// then the LSTM cell update. h is double-buffered by step parity; cross-block
// h reads use __ldcg (L2) since L1 is not coherent across SMs in one launch.
// ---------------------------------------------------------------------------
__device__ __forceinline__ float sigf(float v) {
    return 1.0f / (1.0f + __expf(-v));
}

__global__ void __launch_bounds__(128) lstm_persistent_kernel(
    const float* __restrict__ Whh_f, const float* __restrict__ Whh_b,
    int layer, float* __restrict__ outp, int extra)
{
    const int d = blockIdx.y;
    const int hblk = blockIdx.x * 16;
    const unsigned nb = gridDim.x * gridDim.y;

    const float* __restrict__ W = (d == 0 ? Whh_f : Whh_b) + (size_t)layer * G4 * Hsz;
    float* __restrict__ cst = g_c[d];

    const int tid = threadIdx.x;
    const int hl = tid & 15;        // local h-unit 0..15
    const int b0 = (tid >> 4) * 4;  // 0,4,...,28

    // Zero this block's slice of h (both parities) and c, then barrier.
    for (int i = tid; i < 16 * Bsz; i += 128) {
        int b = i >> 4;
        int idx = b * Hsz + hblk + (i & 15);
        g_h[0][d][idx] = 0.f;
        g_h[1][d][idx] = 0.f;
        g_c[d][idx] = 0.f;
    }
    grid_barrier(nb);

    __shared__ float Hs[32][36];    // [k][b]
    __shared__ float Ws[32][68];    // [k][h_local*4 + gate]

    // load mappings
    const int lb  = tid >> 2;        // 0..31 : b for Hs load
    const int lkv = (tid & 3) * 8;   // 0,8,16,24 : k offset (8 floats)
    const int wc  = tid >> 1;        // 0..63 : smem col for Ws load
    const int wkv = (tid & 1) * 16;  // 0 or 16 : k offset (16 floats)
    const int wj  = (wc & 3) * Hsz + hblk + (wc >> 2); // W row: gate*H + h_global
    const float* __restrict__ wRow = W + (size_t)wj * Hsz;

    for (int s = 0; s < Tsz; s++) {
        const int parity = s & 1;
        const int t = (d == 0) ? s : (Tsz - 1 - s);
        const float* __restrict__ hprev = g_h[parity][d];
        float* __restrict__ hnew = g_h[parity ^ 1][d];
        const float* __restrict__ hRow = hprev + (size_t)lb * Hsz;

        float acc[4][4] = {}; // [b][gate]

        for (int k0 = 0; k0 < Hsz; k0 += 32) {
            float4 h0 = __ldcg((const float4*)(hRow + k0 + lkv));
            float4 h1 = __ldcg((const float4*)(hRow + k0 + lkv + 4));
            Hs[lkv + 0][lb] = h0.x; Hs[lkv + 1][lb] = h0.y;
            Hs[lkv + 2][lb] = h0.z; Hs[lkv + 3][lb] = h0.w;
            Hs[lkv + 4][lb] = h1.x; Hs[lkv + 5][lb] = h1.y;
            Hs[lkv + 6][lb] = h1.z; Hs[lkv + 7][lb] = h1.w;
#pragma unroll
            for (int q = 0; q < 4; q++) {
                float4 w = *(const float4*)(wRow + k0 + wkv + q * 4);
                Ws[wkv + q * 4 + 0][wc] = w.x;
                Ws[wkv + q * 4 + 1][wc] = w.y;
                Ws[wkv + q * 4 + 2][wc] = w.z;
                Ws[wkv + q * 4 + 3][wc] = w.w;
            }
            __syncthreads();
#pragma unroll
            for (int kk = 0; kk < 32; kk++) {
                float4 hv = *(const float4*)&Hs[kk][b0];
                float4 wv = *(const float4*)&Ws[kk][hl * 4];
                acc[0][0] += hv.x * wv.x; acc[0][1] += hv.x * wv.y;
                acc[0][2] += hv.x * wv.z; acc[0][3] += hv.x * wv.w;
                acc[1][0] += hv.y * wv.x; acc[1][1] += hv.y * wv.y;
                acc[1][2] += hv.y * wv.z; acc[1][3] += hv.y * wv.w;
                acc[2][0] += hv.z * wv.x; acc[2][1] += hv.z * wv.y;
                acc[2][2] += hv.z * wv.z; acc[2][3] += hv.z * wv.w;
                acc[3][0] += hv.w * wv.x; acc[3][1] += hv.w * wv.y;
                acc[3][2] += hv.w * wv.z; acc[3][3] += hv.w * wv.w;
            }
            __syncthreads();
        }

        const int hg = hblk + hl;
#pragma unroll
        for (int bi = 0; bi < 4; bi++) {
            int b = b0 + bi;
            const float* __restrict__ Grow = g_G[d] + ((size_t)t * Bsz + b) * G4;
            float gi = acc[bi][0] + Grow[0 * Hsz + hg];
            float gf = acc[bi][1] + Grow[1 * Hsz + hg];
            float gg = acc[bi][2] + Grow[2 * Hsz + hg];
            float go = acc[bi][3] + Grow[3 * Hsz + hg];

            float iv = sigf(gi);
            float fv = sigf(gf);
            float gv = tanhf(gg);
            float ov = sigf(go);

            int idx = b * Hsz + hg;
            float cn = fv * cst[idx] + iv * gv;
            float hn = ov * tanhf(cn);
            cst[idx]  = cn;
            hnew[idx] = hn;

            if (layer == 0) {
                g_seq[d][((size_t)t * Bsz + b) * Hsz + hg] = hn;
            } else {
                // out[b][t][d*H + hg] in [B,T,2H]
                outp[((size_t)b * Tsz + t) * (2 * Hsz) + (size_t)d * Hsz + hg] = hn;
                if (extra) {
                    // fwd buffer then bwd buffer, each [B,T,H]
                    outp[(size_t)Bsz * Tsz * 2 * Hsz + (size_t)d * Bsz * Tsz * Hsz
                         + ((size_t)b * Tsz + t) * Hsz + hg] = hn;
                }
            }
        }

        grid_barrier(nb);  // all h writes visible before next step's reads
    }
}

extern "C" void kernel_launch(void* const* d_in, const int* in_sizes, int n_in,
                              void* d_out, int out_size) {
    const float* x     = (const float*)d_in[0];
    const float* Wih_f = (const float*)d_in[1];
    const float* Whh_f = (const float*)d_in[2];
    const float* b_f   = (const float*)d_in[3];
    const float* Wih_b = (const float*)d_in[4];
    const float* Whh_b = (const float*)d_in[5];
    const float* b_b   = (const float*)d_in[6];
    float* out = (float*)d_out;

    // out pytree: [out(B,T,2H), fwd(B,T,H), bwd(B,T,H)] -> 4*B*T*H total
    const long long full = (long long)Bsz * Tsz * 4 * Hsz;
    int extra = ((long long)out_size >= full) ? 1 : 0;

    dim3 gemmGrid(G4 / 64, MROWS / 64, 2);
    dim3 stepGrid(Hsz / 16, 2);  // 128 blocks <= 148 SMs: all co-resident

    for (int layer = 0; layer < 2; layer++) {
        big_gemm_kernel<<<gemmGrid, 256>>>(x, Wih_f, b_f, Wih_b, b_b, layer);
        lstm_persistent_kernel<<<stepGrid, 128>>>(Whh_f, Whh_b, layer, out, extra);
    }
}

// round 4
// speedup vs baseline: 1.2478x; 1.2478x over previous
#include <cuda_runtime.h>
#include <cuda_bf16.h>
#include <math.h>
#include <stdint.h>

// BiRNN (2-layer bidirectional LSTM), B=32, T=512, H=1024.
// Round 4: input GEMMs via warp-level mma.sync (bf16x3 fp32 emulation) —
// tcgen05 is unavailable (harness compiles for sm_103 base target).
// Recurrent part stays fp32 SIMT persistent kernel.

#define Bsz 32
#define Tsz 512
#define Hsz 1024
#define G4  4096
#define MROWS (Tsz * Bsz) // 16384

// GEMM tiling
#define MT 128
#define NT 128
#define KT 32
#define KP 40                    // smem row pitch in bf16 (80B) -> conflict-free ldmatrix
#define BUFB (MT * KP * 2)       // bytes per matrix buffer (10240)
#define STAGEB (4 * BUFB)        // A_hi, A_lo, B_hi, B_lo
#define SMEM_GEMM (2 * STAGEB)   // 81920

// ---------------- device globals (no runtime allocation) -------------------
__device__ float g_G[2][(size_t)MROWS * G4];            // [dir][r][4H] input gates + bias
__device__ __nv_bfloat16 g_Ahi[2][(size_t)MROWS * Hsz]; // activations hi
__device__ __nv_bfloat16 g_Alo[2][(size_t)MROWS * Hsz]; // activations lo
__device__ __nv_bfloat16 g_Whi[2][(size_t)G4 * Hsz];    // Wih hi (per layer, rewritten)
__device__ __nv_bfloat16 g_Wlo[2][(size_t)G4 * Hsz];
__device__ float g_h[2][2][Bsz * Hsz];                  // [parity][dir][b*H+h]
__device__ float g_c[2][Bsz * Hsz];

__device__ unsigned int g_bar_cnt = 0;
__device__ volatile unsigned int g_bar_gen = 0;

// ---------------- helpers ---------------------------------------------------
__device__ __forceinline__ uint32_t smem_u32(const void* p) {
    uint32_t a;
    asm("{ .reg .u64 t; cvta.to.shared.u64 t, %1; cvt.u32.u64 %0, t; }" : "=r"(a) : "l"(p));
    return a;
}
__device__ __forceinline__ void cp16(uint32_t dst, const void* src) {
    asm volatile("cp.async.cg.shared.global [%0], [%1], 16;" :: "r"(dst), "l"(src));
}
#define CP_COMMIT() asm volatile("cp.async.commit_group;" ::: "memory")
#define CP_WAIT(n)  asm volatile("cp.async.wait_group %0;" :: "n"(n) : "memory")

__device__ __forceinline__ void ldm4(uint32_t* r, uint32_t a) {
    asm volatile("ldmatrix.sync.aligned.m8n8.x4.shared.b16 {%0,%1,%2,%3}, [%4];"
        : "=r"(r[0]), "=r"(r[1]), "=r"(r[2]), "=r"(r[3]) : "r"(a));
}
__device__ __forceinline__ void mma16816(float* d, const uint32_t* a, const uint32_t* b) {
    asm volatile(
        "mma.sync.aligned.m16n8k16.row.col.f32.bf16.bf16.f32 "
        "{%0,%1,%2,%3}, {%4,%5,%6,%7}, {%8,%9}, {%0,%1,%2,%3};"
        : "+f"(d[0]), "+f"(d[1]), "+f"(d[2]), "+f"(d[3])
        : "r"(a[0]), "r"(a[1]), "r"(a[2]), "r"(a[3]), "r"(b[0]), "r"(b[1]));
}

__device__ __forceinline__ void grid_barrier(unsigned nb) {
    __syncthreads();
    if (threadIdx.x == 0) {
        __threadfence();
        unsigned gen = g_bar_gen;
        if (atomicAdd(&g_bar_cnt, 1u) == nb - 1) {
            g_bar_cnt = 0;
            __threadfence();
            g_bar_gen = gen + 1;
        } else {
            while (g_bar_gen == gen) { }
        }
        __threadfence();
    }
    __syncthreads();
}

__device__ __forceinline__ void split_bf16(float v, __nv_bfloat16& hi, __nv_bfloat16& lo) {
    hi = __float2bfloat16(v);
    lo = __float2bfloat16(v - __bfloat162float(hi));
}

// ---------------- conversion kernels ---------------------------------------
__global__ void conv_x_kernel(const float* __restrict__ x) {
    const size_t N = (size_t)MROWS * Hsz;
    for (size_t i = blockIdx.x * blockDim.x + threadIdx.x; i < N; i += (size_t)gridDim.x * blockDim.x) {
        int r = (int)(i >> 10), h = (int)(i & 1023);
        int b = r & 31, t = r >> 5;
        float v = x[((size_t)b * Tsz + t) * Hsz + h];
        __nv_bfloat16 hi, lo; split_bf16(v, hi, lo);
        g_Ahi[0][i] = hi; g_Alo[0][i] = lo;
    }
}

__global__ void conv_w_kernel(const float* __restrict__ Wf, const float* __restrict__ Wb, int layer) {
    const size_t N = (size_t)G4 * Hsz;
    for (size_t i = blockIdx.x * blockDim.x + threadIdx.x; i < 2 * N; i += (size_t)gridDim.x * blockDim.x) {
        int d = i >= N;
        size_t j = d ? i - N : i;
        float v = (d ? Wb : Wf)[(size_t)layer * N + j];
        __nv_bfloat16 hi, lo; split_bf16(v, hi, lo);
        g_Whi[d][j] = hi; g_Wlo[d][j] = lo;
    }
}

// ---------------- HMMA big GEMM --------------------------------------------
// G[d][r][n] = sum_k A[r][k] * W[n][k] + bias[n], bf16x3 (hh + hl + lh).
// Grid (NT blocks = 32, MT blocks = 128, 2 dirs). 256 thr, 8 warps 2x4.
__global__ void __launch_bounds__(256) tc_gemm_kernel(
    const float* __restrict__ b_f, const float* __restrict__ b_b, int layer)
{
    extern __shared__ __align__(16) char sm[];
    const int d = blockIdx.z;
    const int mBlk = blockIdx.y * MT;
    const int nBlk = blockIdx.x * NT;
    const int tid = threadIdx.x, wid = tid >> 5, lid = tid & 31;

    const int aSel = (layer == 0) ? 0 : d;
    const __nv_bfloat16* __restrict__ Ah = g_Ahi[aSel] + (size_t)mBlk * Hsz;
    const __nv_bfloat16* __restrict__ Al = g_Alo[aSel] + (size_t)mBlk * Hsz;
    const __nv_bfloat16* __restrict__ Bh = g_Whi[d] + (size_t)nBlk * Hsz;
    const __nv_bfloat16* __restrict__ Bl = g_Wlo[d] + (size_t)nBlk * Hsz;
    const float* __restrict__ bias = (d == 0 ? b_f : b_b) + (size_t)layer * G4;

    const uint32_t smb = smem_u32(sm);

    // load mapping: 512 16B-chunks per matrix, 2 per thread
    const int lr0 = tid >> 2, lc0 = (tid & 3) * 8;          // row 0..63, col 0/8/16/24
    const int lr1 = (tid + 256) >> 2;                       // row 64..127

    // warp layout
    const int wm = wid & 1, wn = wid >> 1;                  // 2 x 4 warps
    const int ar = lid & 15, acg = lid >> 4;                // A ldmatrix lane mapping
    const int bnr = ((lid & 16) >> 1) | (lid & 7);          // B lane: n row 0-7 / 8-15
    const int bko = lid & 8;                                // B lane: k offset 0/8

    float acc[4][4][4] = {};

    // prologue: stage 0
    {
        const uint32_t base = smb;
        uint32_t d0 = base + (uint32_t)(lr0 * KP + lc0) * 2;
        uint32_t d1 = base + (uint32_t)(lr1 * KP + lc0) * 2;
        size_t s0 = (size_t)lr0 * Hsz + lc0;
        size_t s1 = (size_t)lr1 * Hsz + lc0;
        cp16(d0 + 0 * BUFB, Ah + s0); cp16(d1 + 0 * BUFB, Ah + s1);
        cp16(d0 + 1 * BUFB, Al + s0); cp16(d1 + 1 * BUFB, Al + s1);
        cp16(d0 + 2 * BUFB, Bh + s0); cp16(d1 + 2 * BUFB, Bh + s1);
        cp16(d0 + 3 * BUFB, Bl + s0); cp16(d1 + 3 * BUFB, Bl + s1);
        CP_COMMIT();
    }

    const int NSTG = Hsz / KT; // 32
    for (int s = 0; s < NSTG; s++) {
        if (s + 1 < NSTG) {
            const int k0 = (s + 1) * KT;
            const uint32_t base = smb + ((s + 1) & 1) * STAGEB;
            uint32_t d0 = base + (uint32_t)(lr0 * KP + lc0) * 2;
            uint32_t d1 = base + (uint32_t)(lr1 * KP + lc0) * 2;
            size_t s0 = (size_t)lr0 * Hsz + k0 + lc0;
            size_t s1 = (size_t)lr1 * Hsz + k0 + lc0;
            cp16(d0 + 0 * BUFB, Ah + s0); cp16(d1 + 0 * BUFB, Ah + s1);
            cp16(d0 + 1 * BUFB, Al + s0); cp16(d1 + 1 * BUFB, Al + s1);
            cp16(d0 + 2 * BUFB, Bh + s0); cp16(d1 + 2 * BUFB, Bh + s1);
            cp16(d0 + 3 * BUFB, Bl + s0); cp16(d1 + 3 * BUFB, Bl + s1);
            CP_COMMIT();
            CP_WAIT(1);   // stage s resident
        } else {
            CP_WAIT(0);
        }
        __syncthreads();

        const uint32_t base = smb + (s & 1) * STAGEB;
#pragma unroll
        for (int kc = 0; kc < 2; kc++) {
            uint32_t ah[4][4], al[4][4];
#pragma unroll
            for (int mi = 0; mi < 4; mi++) {
                uint32_t ao = base + (uint32_t)((wm * 64 + mi * 16 + ar) * KP + kc * 16 + acg * 8) * 2;
                ldm4(ah[mi], ao);
                ldm4(al[mi], ao + BUFB);
            }
            uint32_t bh[2][4], bl[2][4];
#pragma unroll
            for (int g = 0; g < 2; g++) {
                uint32_t bo = base + 2 * BUFB
                            + (uint32_t)((wn * 32 + g * 16 + bnr) * KP + kc * 16 + bko) * 2;
                ldm4(bh[g], bo);
                ldm4(bl[g], bo + BUFB);
            }
#pragma unroll
            for (int mi = 0; mi < 4; mi++)
#pragma unroll
                for (int ni = 0; ni < 4; ni++) {
                    const uint32_t* b2h = &bh[ni >> 1][(ni & 1) * 2];
                    const uint32_t* b2l = &bl[ni >> 1][(ni & 1) * 2];
                    mma16816(acc[mi][ni], ah[mi], b2h);
                    mma16816(acc[mi][ni], ah[mi], b2l);
                    mma16816(acc[mi][ni], al[mi], b2h);
                }
        }
        __syncthreads();
    }

    // epilogue
    const int er = lid >> 2, ec = (lid & 3) * 2;
#pragma unroll
    for (int mi = 0; mi < 4; mi++) {
#pragma unroll
        for (int ni = 0; ni < 4; ni++) {
            int gm = mBlk + wm * 64 + mi * 16 + er;
            int gn = nBlk + wn * 32 + ni * 8 + ec;
            float bv0 = bias[gn], bv1 = bias[gn + 1];
            float* p0 = g_G[d] + (size_t)gm * G4 + gn;
            p0[0] = acc[mi][ni][0] + bv0;
            p0[1] = acc[mi][ni][1] + bv1;
            float* p1 = p0 + (size_t)8 * G4;
            p1[0] = acc[mi][ni][2] + bv0;
            p1[1] = acc[mi][ni][3] + bv1;
        }
    }
}

// ---------------- persistent recurrent LSTM --------------------------------
__device__ __forceinline__ float sigf(float v) { return 1.0f / (1.0f + __expf(-v)); }

__global__ void __launch_bounds__(128) lstm_persistent_kernel(
    const float* __restrict__ Whh_f, const float* __restrict__ Whh_b,
    int layer, float* __restrict__ outp, int extra)
{
    const int d = blockIdx.y;
    const int hblk = blockIdx.x * 16;
    const unsigned nb = gridDim.x * gridDim.y;

    const float* __restrict__ W = (d == 0 ? Whh_f : Whh_b) + (size_t)layer * G4 * Hsz;
    float* __restrict__ cst = g_c[d];

    const int tid = threadIdx.x;
    const int hl = tid & 15;
    const int b0 = (tid >> 4) * 4;

    for (int i = tid; i < 16 * Bsz; i += 128) {
        int b = i >> 4;
        int idx = b * Hsz + hblk + (i & 15);
        g_h[0][d][idx] = 0.f;
        g_h[1][d][idx] = 0.f;
        g_c[d][idx] = 0.f;
    }
    grid_barrier(nb);

    __shared__ float Hs[32][36];
    __shared__ float Ws[32][68];

    const int lb  = tid >> 2;
    const int lkv = (tid & 3) * 8;
    const int wc  = tid >> 1;
    const int wkv = (tid & 1) * 16;
    const int wj  = (wc & 3) * Hsz + hblk + (wc >> 2);
    const float* __restrict__ wRow = W + (size_t)wj * Hsz;

    for (int s = 0; s < Tsz; s++) {
        const int parity = s & 1;
        const int t = (d == 0) ? s : (Tsz - 1 - s);
        const float* __restrict__ hprev = g_h[parity][d];
        float* __restrict__ hnew = g_h[parity ^ 1][d];
        const float* __restrict__ hRow = hprev + (size_t)lb * Hsz;

        float acc[4][4] = {};

        for (int k0 = 0; k0 < Hsz; k0 += 32) {
            float4 h0 = __ldcg((const float4*)(hRow + k0 + lkv));
            float4 h1 = __ldcg((const float4*)(hRow + k0 + lkv + 4));
            Hs[lkv + 0][lb] = h0.x; Hs[lkv + 1][lb] = h0.y;
            Hs[lkv + 2][lb] = h0.z; Hs[lkv + 3][lb] = h0.w;
            Hs[lkv + 4][lb] = h1.x; Hs[lkv + 5][lb] = h1.y;
            Hs[lkv + 6][lb] = h1.z; Hs[lkv + 7][lb] = h1.w;
#pragma unroll
            for (int q = 0; q < 4; q++) {
                float4 w = *(const float4*)(wRow + k0 + wkv + q * 4);
                Ws[wkv + q * 4 + 0][wc] = w.x;
                Ws[wkv + q * 4 + 1][wc] = w.y;
                Ws[wkv + q * 4 + 2][wc] = w.z;
                Ws[wkv + q * 4 + 3][wc] = w.w;
            }
            __syncthreads();
#pragma unroll
            for (int kk = 0; kk < 32; kk++) {
                float4 hv = *(const float4*)&Hs[kk][b0];
                float4 wv = *(const float4*)&Ws[kk][hl * 4];
                acc[0][0] += hv.x * wv.x; acc[0][1] += hv.x * wv.y;
                acc[0][2] += hv.x * wv.z; acc[0][3] += hv.x * wv.w;
                acc[1][0] += hv.y * wv.x; acc[1][1] += hv.y * wv.y;
                acc[1][2] += hv.y * wv.z; acc[1][3] += hv.y * wv.w;
                acc[2][0] += hv.z * wv.x; acc[2][1] += hv.z * wv.y;
                acc[2][2] += hv.z * wv.z; acc[2][3] += hv.z * wv.w;
                acc[3][0] += hv.w * wv.x; acc[3][1] += hv.w * wv.y;
                acc[3][2] += hv.w * wv.z; acc[3][3] += hv.w * wv.w;
            }
            __syncthreads();
        }

        const int hg = hblk + hl;
#pragma unroll
        for (int bi = 0; bi < 4; bi++) {
            int b = b0 + bi;
            const float* __restrict__ Grow = g_G[d] + ((size_t)t * Bsz + b) * G4;
            float gi = acc[bi][0] + Grow[0 * Hsz + hg];
            float gf = acc[bi][1] + Grow[1 * Hsz + hg];
            float gg = acc[bi][2] + Grow[2 * Hsz + hg];
            float go = acc[bi][3] + Grow[3 * Hsz + hg];

            float iv = sigf(gi);
            float fv = sigf(gf);
            float gv = tanhf(gg);
            float ov = sigf(go);

            int idx = b * Hsz + hg;
            float cn = fv * cst[idx] + iv * gv;
            float hn = ov * tanhf(cn);
            cst[idx]  = cn;
            hnew[idx] = hn;

            if (layer == 0) {
                __nv_bfloat16 hi, lo; split_bf16(hn, hi, lo);
                size_t off = ((size_t)t * Bsz + b) * Hsz + hg;
                g_Ahi[d][off] = hi;
                g_Alo[d][off] = lo;
            } else {
                outp[((size_t)b * Tsz + t) * (2 * Hsz) + (size_t)d * Hsz + hg] = hn;
                if (extra) {
                    outp[(size_t)Bsz * Tsz * 2 * Hsz + (size_t)d * Bsz * Tsz * Hsz
                         + ((size_t)b * Tsz + t) * Hsz + hg] = hn;
                }
            }
        }

        grid_barrier(nb);
    }
}

extern "C" void kernel_launch(void* const* d_in, const int* in_sizes, int n_in,
                              void* d_out, int out_size) {
    const float* x     = (const float*)d_in[0];
    const float* Wih_f = (const float*)d_in[1];
    const float* Whh_f = (const float*)d_in[2];
    const float* b_f   = (const float*)d_in[3];
    const float* Wih_b = (const float*)d_in[4];
    const float* Whh_b = (const float*)d_in[5];
    const float* b_b   = (const float*)d_in[6];
    float* out = (float*)d_out;

    const long long full = (long long)Bsz * Tsz * 4 * Hsz;
    int extra = ((long long)out_size >= full) ? 1 : 0;

    static int attr_done = 0;
    if (!attr_done) {
        cudaFuncSetAttribute(tc_gemm_kernel,
                             cudaFuncAttributeMaxDynamicSharedMemorySize, SMEM_GEMM);
        attr_done = 1;
    }

    dim3 gemmGrid(G4 / NT, MROWS / MT, 2);   // (32, 128, 2)
    dim3 stepGrid(Hsz / 16, 2);              // 128 blocks, all co-resident

    conv_x_kernel<<<2048, 256>>>(x);
    for (int layer = 0; layer < 2; layer++) {
        conv_w_kernel<<<2048, 256>>>(Wih_f, Wih_b, layer);
        tc_gemm_kernel<<<gemmGrid, 256, SMEM_GEMM>>>(b_f, b_b, layer);
        lstm_persistent_kernel<<<stepGrid, 128>>>(Whh_f, Whh_b, layer, out, extra);
    }
}

// round 5
// speedup vs baseline: 3.1778x; 2.5467x over previous
#include <cuda_runtime.h>
#include <cuda_bf16.h>
#include <math.h>
#include <stdint.h>

// BiRNN (2-layer bidirectional LSTM), B=32, T=512, H=1024.
// Round 5: both the input GEMMs AND the recurrent per-step GEMMs run on
// mma.sync bf16x3 (fp32 emulation: hh + hl + lh). Recurrent is one persistent
// kernel per layer (128 co-resident blocks, software grid barrier per step).

#define Bsz 32
#define Tsz 512
#define Hsz 1024
#define G4  4096
#define MROWS (Tsz * Bsz) // 16384

// big input GEMM tiling
#define MT 128
#define NT 128
#define KT 32
#define KP 40                    // smem pitch bf16 (80B), conflict-free ldmatrix
#define BUFB (MT * KP * 2)       // 10240
#define STAGEB (4 * BUFB)        // A_hi, A_lo, B_hi, B_lo
#define SMEM_GEMM (2 * STAGEB)   // 81920

// recurrent tiling
#define RKP 72                   // bf16 pitch (144B)
#define R_A (32 * RKP * 2)       // 4608
#define R_B (64 * RKP * 2)       // 9216
#define OA_HI 0
#define OA_LO R_A
#define OB_HI (2 * R_A)
#define OB_LO (2 * R_A + R_B)
#define R_STG (2 * R_A + 2 * R_B)   // 27648
#define R_GATES (2 * R_STG)         // 55296
#define GATE_P 68
#define R_C (R_GATES + 32 * GATE_P * 4) // 64000
#define SMEM_R (R_C + 32 * 16 * 4)      // 66048

// ---------------- device globals -------------------------------------------
__device__ float g_G[2][(size_t)MROWS * G4];            // [dir][r][4H] x-part gates + bias
__device__ __nv_bfloat16 g_Ahi[2][(size_t)MROWS * Hsz];
__device__ __nv_bfloat16 g_Alo[2][(size_t)MROWS * Hsz];
__device__ __nv_bfloat16 g_Whi[2][(size_t)G4 * Hsz];    // Wih split (per layer)
__device__ __nv_bfloat16 g_Wlo[2][(size_t)G4 * Hsz];
__device__ __nv_bfloat16 g_Rhi[2][(size_t)G4 * Hsz];    // Whh split + block-reordered
__device__ __nv_bfloat16 g_Rlo[2][(size_t)G4 * Hsz];
__device__ __nv_bfloat16 g_hh[2][2][2][Bsz * Hsz];      // [parity][dir][hi/lo][b*H+k]
__device__ unsigned g_cnt[4][64];                       // split arrival counters (256B apart)
__device__ unsigned g_cnt2;
__device__ volatile unsigned g_gen;

// ---------------- helpers ---------------------------------------------------
__device__ __forceinline__ uint32_t smem_u32(const void* p) {
    uint32_t a;
    asm("{ .reg .u64 t; cvta.to.shared.u64 t, %1; cvt.u32.u64 %0, t; }" : "=r"(a) : "l"(p));
    return a;
}
__device__ __forceinline__ void cp16(uint32_t dst, const void* src) {
    asm volatile("cp.async.cg.shared.global [%0], [%1], 16;" :: "r"(dst), "l"(src));
}
#define CP_COMMIT() asm volatile("cp.async.commit_group;" ::: "memory")
#define CP_WAIT(n)  asm volatile("cp.async.wait_group %0;" :: "n"(n) : "memory")

__device__ __forceinline__ void ldm4(uint32_t* r, uint32_t a) {
    asm volatile("ldmatrix.sync.aligned.m8n8.x4.shared.b16 {%0,%1,%2,%3}, [%4];"
        : "=r"(r[0]), "=r"(r[1]), "=r"(r[2]), "=r"(r[3]) : "r"(a));
}
__device__ __forceinline__ void mma16816(float* d, const uint32_t* a, const uint32_t* b) {
    asm volatile(
        "mma.sync.aligned.m16n8k16.row.col.f32.bf16.bf16.f32 "
        "{%0,%1,%2,%3}, {%4,%5,%6,%7}, {%8,%9}, {%0,%1,%2,%3};"
        : "+f"(d[0]), "+f"(d[1]), "+f"(d[2]), "+f"(d[3])
        : "r"(a[0]), "r"(a[1]), "r"(a[2]), "r"(a[3]), "r"(b[0]), "r"(b[1]));
}

__device__ __forceinline__ void grid_barrier2(int bid) {
    __syncthreads();
    if (threadIdx.x == 0) {
        __threadfence();
        unsigned gen = g_gen;
        unsigned r = atomicAdd(&g_cnt[bid & 3][0], 1u);
        bool released = false;
        if (r == 31) {
            unsigned r2 = atomicAdd(&g_cnt2, 1u);
            if (r2 == 3) {
                g_cnt[0][0] = 0; g_cnt[1][0] = 0; g_cnt[2][0] = 0; g_cnt[3][0] = 0;
                g_cnt2 = 0;
                __threadfence();
                g_gen = gen + 1;
                released = true;
            }
        }
        if (!released) { while (g_gen == gen) { } }
        __threadfence();
    }
    __syncthreads();
}

__device__ __forceinline__ void split_bf16(float v, __nv_bfloat16& hi, __nv_bfloat16& lo) {
    hi = __float2bfloat16(v);
    lo = __float2bfloat16(v - __bfloat162float(hi));
}
__device__ __forceinline__ float sigf(float v) { return 1.0f / (1.0f + __expf(-v)); }

// ---------------- conversion kernels ---------------------------------------
__global__ void conv_x_kernel(const float* __restrict__ x) {
    const size_t N = (size_t)MROWS * Hsz;
    for (size_t i = blockIdx.x * blockDim.x + threadIdx.x; i < N; i += (size_t)gridDim.x * blockDim.x) {
        int r = (int)(i >> 10), h = (int)(i & 1023);
        int b = r & 31, t = r >> 5;
        float v = x[((size_t)b * Tsz + t) * Hsz + h];
        __nv_bfloat16 hi, lo; split_bf16(v, hi, lo);
        g_Ahi[0][i] = hi; g_Alo[0][i] = lo;
    }
}

__global__ void conv_w_kernel(const float* __restrict__ Wf, const float* __restrict__ Wb, int layer) {
    const size_t N = (size_t)G4 * Hsz;
    for (size_t i = blockIdx.x * blockDim.x + threadIdx.x; i < 2 * N; i += (size_t)gridDim.x * blockDim.x) {
        int d = i >= N;
        size_t j = d ? i - N : i;
        float v = (d ? Wb : Wf)[(size_t)layer * N + j];
        __nv_bfloat16 hi, lo; split_bf16(v, hi, lo);
        g_Whi[d][j] = hi; g_Wlo[d][j] = lo;
    }
}

// Whh: split + reorder rows so block x of a dir owns rows [x*64, x*64+64):
// new row = x*64 + gate*16 + hl, where original row = gate*1024 + x*16 + hl.
__global__ void conv_rw_kernel(const float* __restrict__ Wf, const float* __restrict__ Wb, int layer) {
    const size_t N = (size_t)G4 * Hsz;
    for (size_t i = blockIdx.x * blockDim.x + threadIdx.x; i < 2 * N; i += (size_t)gridDim.x * blockDim.x) {
        int d = i >= N;
        size_t j = d ? i - N : i;
        int r = (int)(j >> 10), k = (int)(j & 1023);
        int g = r >> 10, h = r & 1023;
        int xx = h >> 4, hl = h & 15;
        int nr = xx * 64 + g * 16 + hl;
        float v = (d ? Wb : Wf)[(size_t)layer * N + j];
        __nv_bfloat16 hi, lo; split_bf16(v, hi, lo);
        g_Rhi[d][(size_t)nr * Hsz + k] = hi;
        g_Rlo[d][(size_t)nr * Hsz + k] = lo;
    }
}

// ---------------- HMMA big input GEMM --------------------------------------
__global__ void __launch_bounds__(256, 2) tc_gemm_kernel(
    const float* __restrict__ b_f, const float* __restrict__ b_b, int layer)
{
    extern __shared__ __align__(16) char sm[];
    const int d = blockIdx.z;
    const int mBlk = blockIdx.y * MT;
    const int nBlk = blockIdx.x * NT;
    const int tid = threadIdx.x, wid = tid >> 5, lid = tid & 31;

    const int aSel = (layer == 0) ? 0 : d;
    const __nv_bfloat16* __restrict__ Ah = g_Ahi[aSel] + (size_t)mBlk * Hsz;
    const __nv_bfloat16* __restrict__ Al = g_Alo[aSel] + (size_t)mBlk * Hsz;
    const __nv_bfloat16* __restrict__ Bh = g_Whi[d] + (size_t)nBlk * Hsz;
    const __nv_bfloat16* __restrict__ Bl = g_Wlo[d] + (size_t)nBlk * Hsz;
    const float* __restrict__ bias = (d == 0 ? b_f : b_b) + (size_t)layer * G4;

    const uint32_t smb = smem_u32(sm);

    const int lr0 = tid >> 2, lc0 = (tid & 3) * 8;
    const int lr1 = (tid + 256) >> 2;

    const int wm = wid & 1, wn = wid >> 1;
    const int ar = lid & 15, acg = lid >> 4;
    const int bnr = ((lid & 16) >> 1) | (lid & 7);
    const int bko = lid & 8;

    float acc[4][4][4] = {};

    { // prologue stage 0
        const uint32_t base = smb;
        uint32_t d0 = base + (uint32_t)(lr0 * KP + lc0) * 2;
        uint32_t d1 = base + (uint32_t)(lr1 * KP + lc0) * 2;
        size_t s0 = (size_t)lr0 * Hsz + lc0;
        size_t s1 = (size_t)lr1 * Hsz + lc0;
        cp16(d0 + 0 * BUFB, Ah + s0); cp16(d1 + 0 * BUFB, Ah + s1);
        cp16(d0 + 1 * BUFB, Al + s0); cp16(d1 + 1 * BUFB, Al + s1);
        cp16(d0 + 2 * BUFB, Bh + s0); cp16(d1 + 2 * BUFB, Bh + s1);
        cp16(d0 + 3 * BUFB, Bl + s0); cp16(d1 + 3 * BUFB, Bl + s1);
        CP_COMMIT();
    }

    const int NSTG = Hsz / KT; // 32
    for (int s = 0; s < NSTG; s++) {
        if (s + 1 < NSTG) {
            const int k0 = (s + 1) * KT;
            const uint32_t base = smb + ((s + 1) & 1) * STAGEB;
            uint32_t d0 = base + (uint32_t)(lr0 * KP + lc0) * 2;
            uint32_t d1 = base + (uint32_t)(lr1 * KP + lc0) * 2;
            size_t s0 = (size_t)lr0 * Hsz + k0 + lc0;
            size_t s1 = (size_t)lr1 * Hsz + k0 + lc0;
            cp16(d0 + 0 * BUFB, Ah + s0); cp16(d1 + 0 * BUFB, Ah + s1);
            cp16(d0 + 1 * BUFB, Al + s0); cp16(d1 + 1 * BUFB, Al + s1);
            cp16(d0 + 2 * BUFB, Bh + s0); cp16(d1 + 2 * BUFB, Bh + s1);
            cp16(d0 + 3 * BUFB, Bl + s0); cp16(d1 + 3 * BUFB, Bl + s1);
            CP_COMMIT();
            CP_WAIT(1);
        } else {
            CP_WAIT(0);
        }
        __syncthreads();

        const uint32_t base = smb + (s & 1) * STAGEB;
#pragma unroll
        for (int kc = 0; kc < 2; kc++) {
            // phase 1: hi x hi
            uint32_t ah[4][4], bh[2][4];
#pragma unroll
            for (int mi = 0; mi < 4; mi++) {
                uint32_t ao = base + (uint32_t)((wm * 64 + mi * 16 + ar) * KP + kc * 16 + acg * 8) * 2;
                ldm4(ah[mi], ao);
            }
#pragma unroll
            for (int g = 0; g < 2; g++) {
                uint32_t bo = base + 2 * BUFB
                            + (uint32_t)((wn * 32 + g * 16 + bnr) * KP + kc * 16 + bko) * 2;
                ldm4(bh[g], bo);
            }
#pragma unroll
            for (int mi = 0; mi < 4; mi++)
#pragma unroll
                for (int ni = 0; ni < 4; ni++)
                    mma16816(acc[mi][ni], ah[mi], &bh[ni >> 1][(ni & 1) * 2]);
            // phase 2: lo x hi
            {
                uint32_t al[4][4];
#pragma unroll
                for (int mi = 0; mi < 4; mi++) {
                    uint32_t ao = base + BUFB
                                + (uint32_t)((wm * 64 + mi * 16 + ar) * KP + kc * 16 + acg * 8) * 2;
                    ldm4(al[mi], ao);
                }
#pragma unroll
                for (int mi = 0; mi < 4; mi++)
#pragma unroll
                    for (int ni = 0; ni < 4; ni++)
                        mma16816(acc[mi][ni], al[mi], &bh[ni >> 1][(ni & 1) * 2]);
            }
            // phase 3: hi x lo
            {
                uint32_t bl[2][4];
#pragma unroll
                for (int g = 0; g < 2; g++) {
                    uint32_t bo = base + 3 * BUFB
                                + (uint32_t)((wn * 32 + g * 16 + bnr) * KP + kc * 16 + bko) * 2;
                    ldm4(bl[g], bo);
                }
#pragma unroll
                for (int mi = 0; mi < 4; mi++)
#pragma unroll
                    for (int ni = 0; ni < 4; ni++)
                        mma16816(acc[mi][ni], ah[mi], &bl[ni >> 1][(ni & 1) * 2]);
            }
        }
        __syncthreads();
    }

    const int er = lid >> 2, ec = (lid & 3) * 2;
#pragma unroll
    for (int mi = 0; mi < 4; mi++) {
#pragma unroll
        for (int ni = 0; ni < 4; ni++) {
            int gm = mBlk + wm * 64 + mi * 16 + er;
            int gn = nBlk + wn * 32 + ni * 8 + ec;
            float bv0 = bias[gn], bv1 = bias[gn + 1];
            float* p0 = g_G[d] + (size_t)gm * G4 + gn;
            p0[0] = acc[mi][ni][0] + bv0;
            p0[1] = acc[mi][ni][1] + bv1;
            float* p1 = p0 + (size_t)8 * G4;
            p1[0] = acc[mi][ni][2] + bv0;
            p1[1] = acc[mi][ni][3] + bv1;
        }
    }
}

// ---------------- persistent HMMA recurrent LSTM ---------------------------
// Grid (64, 2) = 128 blocks, 256 threads (8 warps: wm = wid&1 m-tile, wn = wid>>1 gate).
// Block (x, d) owns gate cols = reordered rows [x*64, x*64+64) = 16 h-units x 4 gates.
__global__ void __launch_bounds__(256) lstm_hmma_kernel(
    int layer, float* __restrict__ outp, int extra)
{
    extern __shared__ __align__(16) char rsm[];
    const int x = blockIdx.x, d = blockIdx.y;
    const int bid = blockIdx.x + blockIdx.y * 64;
    const int tid = threadIdx.x, wid = tid >> 5, lid = tid & 31;
    const int wm = wid & 1, wn = wid >> 1;

    const uint32_t smb = smem_u32(rsm);
    float* gates_s = (float*)(rsm + R_GATES);
    float* c_s = (float*)(rsm + R_C);

    const __nv_bfloat16* __restrict__ Bh = g_Rhi[d] + (size_t)(x * 64) * Hsz;
    const __nv_bfloat16* __restrict__ Bl = g_Rlo[d] + (size_t)(x * 64) * Hsz;

    // zero h (parity 0 & 1, hi & lo) slice + c smem
    for (int i = tid; i < 512; i += 256) {
        int b = i >> 4, col = x * 16 + (i & 15);
        int idx = b * Hsz + col;
        __nv_bfloat16 z = __float2bfloat16(0.f);
        g_hh[0][d][0][idx] = z; g_hh[0][d][1][idx] = z;
        g_hh[1][d][0][idx] = z; g_hh[1][d][1][idx] = z;
        c_s[i] = 0.f;
    }
    grid_barrier2(bid);

    // load maps
    const int lrA = tid >> 3, lcA = tid & 7;       // A: row 0..31, chunk 0..7
    const int ar = lid & 15, acg = lid >> 4;
    const int bnr = ((lid & 16) >> 1) | (lid & 7);
    const int bko = lid & 8;

    for (int s = 0; s < Tsz; s++) {
        const int p = s & 1;
        const int t = (d == 0) ? s : (Tsz - 1 - s);
        const __nv_bfloat16* __restrict__ Ah = g_hh[p][d][0];
        const __nv_bfloat16* __restrict__ Al = g_hh[p][d][1];

        float accA[2][4] = {};   // hi x hi
        float accB[2][4] = {};   // lo x hi + hi x lo

        // prologue: k-tile 0
        {
            const uint32_t base = smb;
            uint32_t dA = base + (uint32_t)(lrA * (RKP * 2) + lcA * 16);
            const size_t sA = (size_t)lrA * Hsz + lcA * 8;
            cp16(dA + OA_HI, Ah + sA);
            cp16(dA + OA_LO, Al + sA);
            uint32_t dB = base + OB_HI + (uint32_t)(lrA * (RKP * 2) + lcA * 16);
            cp16(dB, Bh + sA);
            cp16(dB + 32 * (RKP * 2), Bh + sA + (size_t)32 * Hsz);
            uint32_t dB2 = base + OB_LO + (uint32_t)(lrA * (RKP * 2) + lcA * 16);
            cp16(dB2, Bl + sA);
            cp16(dB2 + 32 * (RKP * 2), Bl + sA + (size_t)32 * Hsz);
            CP_COMMIT();
        }

        for (int kt = 0; kt < 16; kt++) {
            if (kt + 1 < 16) {
                const uint32_t base = smb + ((kt + 1) & 1) * R_STG;
                const int k0 = (kt + 1) * 64;
                uint32_t dA = base + (uint32_t)(lrA * (RKP * 2) + lcA * 16);
                const size_t sA = (size_t)lrA * Hsz + k0 + lcA * 8;
                cp16(dA + OA_HI, Ah + sA);
                cp16(dA + OA_LO, Al + sA);
                uint32_t dB = base + OB_HI + (uint32_t)(lrA * (RKP * 2) + lcA * 16);
                cp16(dB, Bh + sA);
                cp16(dB + 32 * (RKP * 2), Bh + sA + (size_t)32 * Hsz);
                uint32_t dB2 = base + OB_LO + (uint32_t)(lrA * (RKP * 2) + lcA * 16);
                cp16(dB2, Bl + sA);
                cp16(dB2 + 32 * (RKP * 2), Bl + sA + (size_t)32 * Hsz);
                CP_COMMIT();
                CP_WAIT(1);
            } else {
                CP_WAIT(0);
            }
            __syncthreads();

            const uint32_t base = smb + (kt & 1) * R_STG;
#pragma unroll
            for (int kc = 0; kc < 4; kc++) {
                uint32_t ah[4], al[4], bh[4], bl[4];
                uint32_t ao = base + (uint32_t)((wm * 16 + ar) * RKP + kc * 16 + acg * 8) * 2;
                ldm4(ah, ao + OA_HI);
                ldm4(al, ao + OA_LO);
                uint32_t bo = base + (uint32_t)((wn * 16 + bnr) * RKP + kc * 16 + bko) * 2;
                ldm4(bh, bo + OB_HI);
                ldm4(bl, bo + OB_LO);
                mma16816(accA[0], ah, &bh[0]);
                mma16816(accA[1], ah, &bh[2]);
                mma16816(accB[0], al, &bh[0]);
                mma16816(accB[1], al, &bh[2]);
                mma16816(accB[0], ah, &bl[0]);
                mma16816(accB[1], ah, &bl[2]);
            }
            __syncthreads();
        }

        // epilogue: add G, store gates to smem
        {
            const int er = lid >> 2, ec = (lid & 3) * 2;
#pragma unroll
            for (int ni = 0; ni < 2; ni++) {
#pragma unroll
                for (int half = 0; half < 2; half++) {
                    int b = wm * 16 + er + half * 8;
                    int hl = ni * 8 + ec;
                    const float* gp = g_G[d] + (size_t)(t * 32 + b) * G4 + wn * 1024 + x * 16 + hl;
                    float2 gv = *(const float2*)gp;
                    gates_s[b * GATE_P + wn * 16 + hl]     = accA[ni][half * 2 + 0] + accB[ni][half * 2 + 0] + gv.x;
                    gates_s[b * GATE_P + wn * 16 + hl + 1] = accA[ni][half * 2 + 1] + accB[ni][half * 2 + 1] + gv.y;
                }
            }
        }
        __syncthreads();

        // cell update: thread handles (b, hl2) and (b, hl2+1)
        {
            const int b = tid >> 3;
            const int hl2 = (tid & 7) * 2;
            const int np = p ^ 1;
#pragma unroll
            for (int u = 0; u < 2; u++) {
                int hl = hl2 + u;
                float gi = gates_s[b * GATE_P + 0 * 16 + hl];
                float gf = gates_s[b * GATE_P + 1 * 16 + hl];
                float gg = gates_s[b * GATE_P + 2 * 16 + hl];
                float go = gates_s[b * GATE_P + 3 * 16 + hl];
                float iv = sigf(gi), fv = sigf(gf), gv = tanhf(gg), ov = sigf(go);
                float cc = c_s[b * 16 + hl];
                float cn = fv * cc + iv * gv;
                float hn = ov * tanhf(cn);
                c_s[b * 16 + hl] = cn;

                int col = x * 16 + hl;
                __nv_bfloat16 hi, lo; split_bf16(hn, hi, lo);
                g_hh[np][d][0][b * Hsz + col] = hi;
                g_hh[np][d][1][b * Hsz + col] = lo;

                if (layer == 0) {
                    size_t off = (size_t)(t * 32 + b) * Hsz + col;
                    g_Ahi[d][off] = hi;
                    g_Alo[d][off] = lo;
                } else {
                    outp[((size_t)b * Tsz + t) * (2 * Hsz) + (size_t)d * Hsz + col] = hn;
                    if (extra) {
                        outp[(size_t)Bsz * Tsz * 2 * Hsz + (size_t)d * Bsz * Tsz * Hsz
                             + ((size_t)b * Tsz + t) * Hsz + col] = hn;
                    }
                }
            }
        }

        grid_barrier2(bid);
    }
}

extern "C" void kernel_launch(void* const* d_in, const int* in_sizes, int n_in,
                              void* d_out, int out_size) {
    const float* x     = (const float*)d_in[0];
    const float* Wih_f = (const float*)d_in[1];
    const float* Whh_f = (const float*)d_in[2];
    const float* b_f   = (const float*)d_in[3];
    const float* Wih_b = (const float*)d_in[4];
    const float* Whh_b = (const float*)d_in[5];
    const float* b_b   = (const float*)d_in[6];
    float* out = (float*)d_out;

    const long long full = (long long)Bsz * Tsz * 4 * Hsz;
    int extra = ((long long)out_size >= full) ? 1 : 0;

    static int attr_done = 0;
    if (!attr_done) {
        cudaFuncSetAttribute(tc_gemm_kernel,
                             cudaFuncAttributeMaxDynamicSharedMemorySize, SMEM_GEMM);
        cudaFuncSetAttribute(lstm_hmma_kernel,
                             cudaFuncAttributeMaxDynamicSharedMemorySize, SMEM_R);
        attr_done = 1;
    }

    dim3 gemmGrid(G4 / NT, MROWS / MT, 2);   // (32, 128, 2)
    dim3 stepGrid(64, 2);                    // 128 co-resident blocks

    conv_x_kernel<<<2048, 256>>>(x);
    for (int layer = 0; layer < 2; layer++) {
        conv_w_kernel<<<2048, 256>>>(Wih_f, Wih_b, layer);
        conv_rw_kernel<<<2048, 256>>>(Whh_f, Whh_b, layer);
        tc_gemm_kernel<<<gemmGrid, 256, SMEM_GEMM>>>(b_f, b_b, layer);
        lstm_hmma_kernel<<<stepGrid, 256, SMEM_R>>>(layer, out, extra);
    }
}

// round 6
// speedup vs baseline: 3.5611x; 1.1206x over previous
#include <cuda_runtime.h>
#include <cuda_bf16.h>
#include <math.h>
#include <stdint.h>

// BiRNN (2-layer bidirectional LSTM), B=32, T=512, H=1024.
// Round 6: recurrent kernel rebuilt — Whh_hi resident in smem, 3-stage
// cp.async pipeline, single __syncthreads per k-tile. Input GEMM unchanged.

#define Bsz 32
#define Tsz 512
#define Hsz 1024
#define G4  4096
#define MROWS (Tsz * Bsz) // 16384

// big input GEMM tiling
#define MT 128
#define NT 128
#define KT 32
#define KP 40
#define BUFB (MT * KP * 2)
#define STAGEB (4 * BUFB)
#define SMEM_GEMM (2 * STAGEB)   // 81920

// recurrent tiling
#define RKP 72                          // bf16 pitch (144B) -> conflict-free ldmatrix
#define R_TILEB (64 * RKP * 2)          // one 64x64 B tile: 9216 B
#define R_BHRES (16 * R_TILEB)          // resident Whh_hi: 147456
#define R_SA (32 * RKP * 2)             // A (h) tile: 4608
#define R_STG2 (2 * R_SA + R_TILEB)     // stage: A_hi, A_lo, B_lo = 18432
#define R_NSTG 3
#define R_GATES2 (R_BHRES + R_NSTG * R_STG2)  // 202752
#define GATE_P 68
#define R_C2 (R_GATES2 + 32 * GATE_P * 4)     // 211456
#define SMEM_R2 (R_C2 + 32 * 16 * 4)          // 213504

// ---------------- device globals -------------------------------------------
__device__ float g_G[2][(size_t)MROWS * G4];
__device__ __nv_bfloat16 g_Ahi[2][(size_t)MROWS * Hsz];
__device__ __nv_bfloat16 g_Alo[2][(size_t)MROWS * Hsz];
__device__ __nv_bfloat16 g_Whi[2][(size_t)G4 * Hsz];
__device__ __nv_bfloat16 g_Wlo[2][(size_t)G4 * Hsz];
__device__ __nv_bfloat16 g_Rhi[2][(size_t)G4 * Hsz];    // Whh split + block-reordered
__device__ __nv_bfloat16 g_Rlo[2][(size_t)G4 * Hsz];
__device__ __nv_bfloat16 g_hh[2][2][2][Bsz * Hsz];      // [parity][dir][hi/lo][b*H+k]
__device__ unsigned g_cnt[4][64];
__device__ unsigned g_cnt2;
__device__ volatile unsigned g_gen;

// ---------------- helpers ---------------------------------------------------
__device__ __forceinline__ uint32_t smem_u32(const void* p) {
    uint32_t a;
    asm("{ .reg .u64 t; cvta.to.shared.u64 t, %1; cvt.u32.u64 %0, t; }" : "=r"(a) : "l"(p));
    return a;
}
__device__ __forceinline__ void cp16(uint32_t dst, const void* src) {
    asm volatile("cp.async.cg.shared.global [%0], [%1], 16;" :: "r"(dst), "l"(src));
}
#define CP_COMMIT() asm volatile("cp.async.commit_group;" ::: "memory")
#define CP_WAIT(n)  asm volatile("cp.async.wait_group %0;" :: "n"(n) : "memory")

__device__ __forceinline__ void ldm4(uint32_t* r, uint32_t a) {
    asm volatile("ldmatrix.sync.aligned.m8n8.x4.shared.b16 {%0,%1,%2,%3}, [%4];"
        : "=r"(r[0]), "=r"(r[1]), "=r"(r[2]), "=r"(r[3]) : "r"(a));
}
__device__ __forceinline__ void mma16816(float* d, const uint32_t* a, const uint32_t* b) {
    asm volatile(
        "mma.sync.aligned.m16n8k16.row.col.f32.bf16.bf16.f32 "
        "{%0,%1,%2,%3}, {%4,%5,%6,%7}, {%8,%9}, {%0,%1,%2,%3};"
        : "+f"(d[0]), "+f"(d[1]), "+f"(d[2]), "+f"(d[3])
        : "r"(a[0]), "r"(a[1]), "r"(a[2]), "r"(a[3]), "r"(b[0]), "r"(b[1]));
}

__device__ __forceinline__ void grid_barrier2(int bid) {
    __syncthreads();
    if (threadIdx.x == 0) {
        __threadfence();
        unsigned gen = g_gen;
        unsigned r = atomicAdd(&g_cnt[bid & 3][0], 1u);
        bool released = false;
        if (r == 31) {
            unsigned r2 = atomicAdd(&g_cnt2, 1u);
            if (r2 == 3) {
                g_cnt[0][0] = 0; g_cnt[1][0] = 0; g_cnt[2][0] = 0; g_cnt[3][0] = 0;
                g_cnt2 = 0;
                __threadfence();
                g_gen = gen + 1;
                released = true;
            }
        }
        if (!released) { while (g_gen == gen) { } }
        __threadfence();
    }
    __syncthreads();
}

__device__ __forceinline__ void split_bf16(float v, __nv_bfloat16& hi, __nv_bfloat16& lo) {
    hi = __float2bfloat16(v);
    lo = __float2bfloat16(v - __bfloat162float(hi));
}
__device__ __forceinline__ float sigf(float v) { return 1.0f / (1.0f + __expf(-v)); }

// ---------------- conversion kernels ---------------------------------------
__global__ void conv_x_kernel(const float* __restrict__ x) {
    const size_t N = (size_t)MROWS * Hsz;
    for (size_t i = blockIdx.x * blockDim.x + threadIdx.x; i < N; i += (size_t)gridDim.x * blockDim.x) {
        int r = (int)(i >> 10), h = (int)(i & 1023);
        int b = r & 31, t = r >> 5;
        float v = x[((size_t)b * Tsz + t) * Hsz + h];
        __nv_bfloat16 hi, lo; split_bf16(v, hi, lo);
        g_Ahi[0][i] = hi; g_Alo[0][i] = lo;
    }
}

__global__ void conv_w_kernel(const float* __restrict__ Wf, const float* __restrict__ Wb, int layer) {
    const size_t N = (size_t)G4 * Hsz;
    for (size_t i = blockIdx.x * blockDim.x + threadIdx.x; i < 2 * N; i += (size_t)gridDim.x * blockDim.x) {
        int d = i >= N;
        size_t j = d ? i - N : i;
        float v = (d ? Wb : Wf)[(size_t)layer * N + j];
        __nv_bfloat16 hi, lo; split_bf16(v, hi, lo);
        g_Whi[d][j] = hi; g_Wlo[d][j] = lo;
    }
}

__global__ void conv_rw_kernel(const float* __restrict__ Wf, const float* __restrict__ Wb, int layer) {
    const size_t N = (size_t)G4 * Hsz;
    for (size_t i = blockIdx.x * blockDim.x + threadIdx.x; i < 2 * N; i += (size_t)gridDim.x * blockDim.x) {
        int d = i >= N;
        size_t j = d ? i - N : i;
        int r = (int)(j >> 10), k = (int)(j & 1023);
        int g = r >> 10, h = r & 1023;
        int xx = h >> 4, hl = h & 15;
        int nr = xx * 64 + g * 16 + hl;
        float v = (d ? Wb : Wf)[(size_t)layer * N + j];
        __nv_bfloat16 hi, lo; split_bf16(v, hi, lo);
        g_Rhi[d][(size_t)nr * Hsz + k] = hi;
        g_Rlo[d][(size_t)nr * Hsz + k] = lo;
    }
}

// ---------------- HMMA big input GEMM (unchanged) --------------------------
__global__ void __launch_bounds__(256, 2) tc_gemm_kernel(
    const float* __restrict__ b_f, const float* __restrict__ b_b, int layer)
{
    extern __shared__ __align__(16) char sm[];
    const int d = blockIdx.z;
    const int mBlk = blockIdx.y * MT;
    const int nBlk = blockIdx.x * NT;
    const int tid = threadIdx.x, wid = tid >> 5, lid = tid & 31;

    const int aSel = (layer == 0) ? 0 : d;
    const __nv_bfloat16* __restrict__ Ah = g_Ahi[aSel] + (size_t)mBlk * Hsz;
    const __nv_bfloat16* __restrict__ Al = g_Alo[aSel] + (size_t)mBlk * Hsz;
    const __nv_bfloat16* __restrict__ Bh = g_Whi[d] + (size_t)nBlk * Hsz;
    const __nv_bfloat16* __restrict__ Bl = g_Wlo[d] + (size_t)nBlk * Hsz;
    const float* __restrict__ bias = (d == 0 ? b_f : b_b) + (size_t)layer * G4;

    const uint32_t smb = smem_u32(sm);

    const int lr0 = tid >> 2, lc0 = (tid & 3) * 8;
    const int lr1 = (tid + 256) >> 2;

    const int wm = wid & 1, wn = wid >> 1;
    const int ar = lid & 15, acg = lid >> 4;
    const int bnr = ((lid & 16) >> 1) | (lid & 7);
    const int bko = lid & 8;

    float acc[4][4][4] = {};

    {
        const uint32_t base = smb;
        uint32_t d0 = base + (uint32_t)(lr0 * KP + lc0) * 2;
        uint32_t d1 = base + (uint32_t)(lr1 * KP + lc0) * 2;
        size_t s0 = (size_t)lr0 * Hsz + lc0;
        size_t s1 = (size_t)lr1 * Hsz + lc0;
        cp16(d0 + 0 * BUFB, Ah + s0); cp16(d1 + 0 * BUFB, Ah + s1);
        cp16(d0 + 1 * BUFB, Al + s0); cp16(d1 + 1 * BUFB, Al + s1);
        cp16(d0 + 2 * BUFB, Bh + s0); cp16(d1 + 2 * BUFB, Bh + s1);
        cp16(d0 + 3 * BUFB, Bl + s0); cp16(d1 + 3 * BUFB, Bl + s1);
        CP_COMMIT();
    }

    const int NSTG = Hsz / KT; // 32
    for (int s = 0; s < NSTG; s++) {
        if (s + 1 < NSTG) {
            const int k0 = (s + 1) * KT;
            const uint32_t base = smb + ((s + 1) & 1) * STAGEB;
            uint32_t d0 = base + (uint32_t)(lr0 * KP + lc0) * 2;
            uint32_t d1 = base + (uint32_t)(lr1 * KP + lc0) * 2;
            size_t s0 = (size_t)lr0 * Hsz + k0 + lc0;
            size_t s1 = (size_t)lr1 * Hsz + k0 + lc0;
            cp16(d0 + 0 * BUFB, Ah + s0); cp16(d1 + 0 * BUFB, Ah + s1);
            cp16(d0 + 1 * BUFB, Al + s0); cp16(d1 + 1 * BUFB, Al + s1);
            cp16(d0 + 2 * BUFB, Bh + s0); cp16(d1 + 2 * BUFB, Bh + s1);
            cp16(d0 + 3 * BUFB, Bl + s0); cp16(d1 + 3 * BUFB, Bl + s1);
            CP_COMMIT();
            CP_WAIT(1);
        } else {
            CP_WAIT(0);
        }
        __syncthreads();

        const uint32_t base = smb + (s & 1) * STAGEB;
#pragma unroll
        for (int kc = 0; kc < 2; kc++) {
            uint32_t ah[4][4], bh[2][4];
#pragma unroll
            for (int mi = 0; mi < 4; mi++) {
                uint32_t ao = base + (uint32_t)((wm * 64 + mi * 16 + ar) * KP + kc * 16 + acg * 8) * 2;
                ldm4(ah[mi], ao);
            }
#pragma unroll
            for (int g = 0; g < 2; g++) {
                uint32_t bo = base + 2 * BUFB
                            + (uint32_t)((wn * 32 + g * 16 + bnr) * KP + kc * 16 + bko) * 2;
                ldm4(bh[g], bo);
            }
#pragma unroll
            for (int mi = 0; mi < 4; mi++)
#pragma unroll
                for (int ni = 0; ni < 4; ni++)
                    mma16816(acc[mi][ni], ah[mi], &bh[ni >> 1][(ni & 1) * 2]);
            {
                uint32_t al[4][4];
#pragma unroll
                for (int mi = 0; mi < 4; mi++) {
                    uint32_t ao = base + BUFB
                                + (uint32_t)((wm * 64 + mi * 16 + ar) * KP + kc * 16 + acg * 8) * 2;
                    ldm4(al[mi], ao);
                }
#pragma unroll
                for (int mi = 0; mi < 4; mi++)
#pragma unroll
                    for (int ni = 0; ni < 4; ni++)
                        mma16816(acc[mi][ni], al[mi], &bh[ni >> 1][(ni & 1) * 2]);
            }
            {
                uint32_t bl[2][4];
#pragma unroll
                for (int g = 0; g < 2; g++) {
                    uint32_t bo = base + 3 * BUFB
                                + (uint32_t)((wn * 32 + g * 16 + bnr) * KP + kc * 16 + bko) * 2;
                    ldm4(bl[g], bo);
                }
#pragma unroll
                for (int mi = 0; mi < 4; mi++)
#pragma unroll
                    for (int ni = 0; ni < 4; ni++)
                        mma16816(acc[mi][ni], ah[mi], &bl[ni >> 1][(ni & 1) * 2]);
            }
        }
        __syncthreads();
    }

    const int er = lid >> 2, ec = (lid & 3) * 2;
#pragma unroll
    for (int mi = 0; mi < 4; mi++) {
#pragma unroll
        for (int ni = 0; ni < 4; ni++) {
            int gm = mBlk + wm * 64 + mi * 16 + er;
            int gn = nBlk + wn * 32 + ni * 8 + ec;
            float bv0 = bias[gn], bv1 = bias[gn + 1];
            float* p0 = g_G[d] + (size_t)gm * G4 + gn;
            p0[0] = acc[mi][ni][0] + bv0;
            p0[1] = acc[mi][ni][1] + bv1;
            float* p1 = p0 + (size_t)8 * G4;
            p1[0] = acc[mi][ni][2] + bv0;
            p1[1] = acc[mi][ni][3] + bv1;
        }
    }
}

// ---------------- persistent HMMA recurrent LSTM ---------------------------
// Grid (64, 2) = 128 blocks, 256 thr. Whh_hi resident in smem; {h_hi, h_lo,
// Whh_lo} streamed through a 3-stage cp.async pipeline, 1 sync per k-tile.
__global__ void __launch_bounds__(256) lstm_hmma_kernel(
    int layer, float* __restrict__ outp, int extra)
{
    extern __shared__ __align__(16) char rsm[];
    const int x = blockIdx.x, d = blockIdx.y;
    const int bid = blockIdx.x + blockIdx.y * 64;
    const int tid = threadIdx.x, wid = tid >> 5, lid = tid & 31;
    const int wm = wid & 1, wn = wid >> 1;

    const uint32_t smb = smem_u32(rsm);
    float* gates_s = (float*)(rsm + R_GATES2);
    float* c_s = (float*)(rsm + R_C2);

    const __nv_bfloat16* __restrict__ Bh = g_Rhi[d] + (size_t)(x * 64) * Hsz;
    const __nv_bfloat16* __restrict__ Bl = g_Rlo[d] + (size_t)(x * 64) * Hsz;

    const int lrow = tid >> 3, lc = tid & 7;    // row 0..31, 16B chunk 0..7

    // Preload resident Whh_hi (16 k-tiles of 64x64) while zeroing state.
#pragma unroll 4
    for (int kt = 0; kt < 16; kt++) {
        uint32_t dst = smb + kt * R_TILEB + (uint32_t)(lrow * (RKP * 2) + lc * 16);
        const __nv_bfloat16* src = Bh + (size_t)lrow * Hsz + kt * 64 + lc * 8;
        cp16(dst, src);
        cp16(dst + 32 * (RKP * 2), src + (size_t)32 * Hsz);
    }
    CP_COMMIT();

    for (int i = tid; i < 512; i += 256) {
        int b = i >> 4, col = x * 16 + (i & 15);
        int idx = b * Hsz + col;
        __nv_bfloat16 z = __float2bfloat16(0.f);
        g_hh[0][d][0][idx] = z; g_hh[0][d][1][idx] = z;
        g_hh[1][d][0][idx] = z; g_hh[1][d][1][idx] = z;
        c_s[i] = 0.f;
    }
    CP_WAIT(0);
    grid_barrier2(bid);

    const int ar = lid & 15, acg = lid >> 4;
    const int bnr = ((lid & 16) >> 1) | (lid & 7);
    const int bko = lid & 8;

    const uint32_t stgbase = smb + R_BHRES;
    const uint32_t doffA = (uint32_t)(lrow * (RKP * 2) + lc * 16);

    for (int s = 0; s < Tsz; s++) {
        const int p = s & 1;
        const int t = (d == 0) ? s : (Tsz - 1 - s);
        const __nv_bfloat16* __restrict__ Ah = g_hh[p][d][0];
        const __nv_bfloat16* __restrict__ Al = g_hh[p][d][1];

        float accA[2][4] = {};
        float accB[2][4] = {};

        // issue k-tiles 0 and 1
#pragma unroll
        for (int kt = 0; kt < 2; kt++) {
            const uint32_t base = stgbase + kt * R_STG2;
            const size_t soff = (size_t)lrow * Hsz + kt * 64 + lc * 8;
            cp16(base + doffA, Ah + soff);
            cp16(base + R_SA + doffA, Al + soff);
            cp16(base + 2 * R_SA + doffA, Bl + soff);
            cp16(base + 2 * R_SA + doffA + 32 * (RKP * 2), Bl + soff + (size_t)32 * Hsz);
            CP_COMMIT();
        }

        for (int kt = 0; kt < 16; kt++) {
            if (kt < 15) { CP_WAIT(1); } else { CP_WAIT(0); }
            __syncthreads();
            if (kt < 14) {
                const int kn = kt + 2;
                const uint32_t base = stgbase + (kn % 3) * R_STG2;
                const size_t soff = (size_t)lrow * Hsz + kn * 64 + lc * 8;
                cp16(base + doffA, Ah + soff);
                cp16(base + R_SA + doffA, Al + soff);
                cp16(base + 2 * R_SA + doffA, Bl + soff);
                cp16(base + 2 * R_SA + doffA + 32 * (RKP * 2), Bl + soff + (size_t)32 * Hsz);
                CP_COMMIT();
            }

            const uint32_t stg = stgbase + (kt % 3) * R_STG2;
            const uint32_t bres = smb + kt * R_TILEB;
#pragma unroll
            for (int kc = 0; kc < 4; kc++) {
                uint32_t ah[4], al[4], bh[4], bl[4];
                uint32_t ao = stg + (uint32_t)((wm * 16 + ar) * RKP + kc * 16 + acg * 8) * 2;
                ldm4(ah, ao);
                ldm4(al, ao + R_SA);
                uint32_t bo = (uint32_t)((wn * 16 + bnr) * RKP + kc * 16 + bko) * 2;
                ldm4(bh, bres + bo);
                ldm4(bl, stg + 2 * R_SA + bo);
                mma16816(accA[0], ah, &bh[0]);
                mma16816(accA[1], ah, &bh[2]);
                mma16816(accB[0], al, &bh[0]);
                mma16816(accB[1], al, &bh[2]);
                mma16816(accB[0], ah, &bl[0]);
                mma16816(accB[1], ah, &bl[2]);
            }
        }
        __syncthreads();

        // epilogue: add G, store gates to smem
        {
            const int er = lid >> 2, ec = (lid & 3) * 2;
#pragma unroll
            for (int ni = 0; ni < 2; ni++) {
#pragma unroll
                for (int half = 0; half < 2; half++) {
                    int b = wm * 16 + er + half * 8;
                    int hl = ni * 8 + ec;
                    const float* gp = g_G[d] + (size_t)(t * 32 + b) * G4 + wn * 1024 + x * 16 + hl;
                    float2 gv = *(const float2*)gp;
                    gates_s[b * GATE_P + wn * 16 + hl]     = accA[ni][half * 2 + 0] + accB[ni][half * 2 + 0] + gv.x;
                    gates_s[b * GATE_P + wn * 16 + hl + 1] = accA[ni][half * 2 + 1] + accB[ni][half * 2 + 1] + gv.y;
                }
            }
        }
        __syncthreads();

        // cell update
        {
            const int b = tid >> 3;
            const int hl2 = (tid & 7) * 2;
            const int np = p ^ 1;
#pragma unroll
            for (int u = 0; u < 2; u++) {
                int hl = hl2 + u;
                float gi = gates_s[b * GATE_P + 0 * 16 + hl];
                float gf = gates_s[b * GATE_P + 1 * 16 + hl];
                float gg = gates_s[b * GATE_P + 2 * 16 + hl];
                float go = gates_s[b * GATE_P + 3 * 16 + hl];
                float iv = sigf(gi), fv = sigf(gf), gv = tanhf(gg), ov = sigf(go);
                float cc = c_s[b * 16 + hl];
                float cn = fv * cc + iv * gv;
                float hn = ov * tanhf(cn);
                c_s[b * 16 + hl] = cn;

                int col = x * 16 + hl;
                __nv_bfloat16 hi, lo; split_bf16(hn, hi, lo);
                g_hh[np][d][0][b * Hsz + col] = hi;
                g_hh[np][d][1][b * Hsz + col] = lo;

                if (layer == 0) {
                    size_t off = (size_t)(t * 32 + b) * Hsz + col;
                    g_Ahi[d][off] = hi;
                    g_Alo[d][off] = lo;
                } else {
                    outp[((size_t)b * Tsz + t) * (2 * Hsz) + (size_t)d * Hsz + col] = hn;
                    if (extra) {
                        outp[(size_t)Bsz * Tsz * 2 * Hsz + (size_t)d * Bsz * Tsz * Hsz
                             + ((size_t)b * Tsz + t) * Hsz + col] = hn;
                    }
                }
            }
        }

        grid_barrier2(bid);
    }
}

extern "C" void kernel_launch(void* const* d_in, const int* in_sizes, int n_in,
                              void* d_out, int out_size) {
    const float* x     = (const float*)d_in[0];
    const float* Wih_f = (const float*)d_in[1];
    const float* Whh_f = (const float*)d_in[2];
    const float* b_f   = (const float*)d_in[3];
    const float* Wih_b = (const float*)d_in[4];
    const float* Whh_b = (const float*)d_in[5];
    const float* b_b   = (const float*)d_in[6];
    float* out = (float*)d_out;

    const long long full = (long long)Bsz * Tsz * 4 * Hsz;
    int extra = ((long long)out_size >= full) ? 1 : 0;

    static int attr_done = 0;
    if (!attr_done) {
        cudaFuncSetAttribute(tc_gemm_kernel,
                             cudaFuncAttributeMaxDynamicSharedMemorySize, SMEM_GEMM);
        cudaFuncSetAttribute(lstm_hmma_kernel,
                             cudaFuncAttributeMaxDynamicSharedMemorySize, SMEM_R2);
        attr_done = 1;
    }

    dim3 gemmGrid(G4 / NT, MROWS / MT, 2);   // (32, 128, 2)
    dim3 stepGrid(64, 2);                    // 128 co-resident blocks

    conv_x_kernel<<<2048, 256>>>(x);
    for (int layer = 0; layer < 2; layer++) {
        conv_w_kernel<<<2048, 256>>>(Wih_f, Wih_b, layer);
        conv_rw_kernel<<<2048, 256>>>(Whh_f, Whh_b, layer);
        tc_gemm_kernel<<<gemmGrid, 256, SMEM_GEMM>>>(b_f, b_b, layer);
        lstm_hmma_kernel<<<stepGrid, 256, SMEM_R2>>>(layer, out, extra);
    }
}